// round 16
// baseline (speedup 1.0000x reference)
#include <cuda_runtime.h>
#include <cstdint>

#define NN   100000
#define EE   1600000
#define EP   1700000   // EE + NN self loops
#define HH   4
#define CC   32
#define HC   128
#define EDD  16
#define NBLK ((NN + 255) / 256)

// ---------------- scratch: device symbols -----------------------------------
static __device__ int   g_degi[NN];
static __device__ int   g_bsum[NBLK];
static __device__ int   g_rowptr[NN + 1];
static __device__ int   g_cursor[NN];
static __device__ __align__(8) int2 g_cpack[EP];                 // (src, eid)
static __device__ __align__(16) float g_edot1[(size_t)EE * HH];
static __device__ float g_edot2[EE];
static __device__ __align__(16) float g_sdot1[(size_t)NN * HH];
static __device__ float g_sdot2[NN];
static __device__ __align__(16) float g_feat1[(size_t)NN * HC];
static __device__ __align__(16) float g_h1[(size_t)NN * HC];
static __device__ __align__(16) float g_feat2[(size_t)NN * CC];
static __device__ __align__(16) float g_als1[(size_t)NN * HH];
static __device__ __align__(16) float g_ald1[(size_t)NN * HH];
static __device__ float g_als2[NN];
static __device__ float g_ald2[NN];
static __device__ float g_eb2[EP];                                // p2 (for alpha out)
static __device__ float g_z2[NN];
static __device__ float g_ve1[EDD * HH];
static __device__ float g_ve2[EDD];
static __device__ float g_alpha_scratch[EP];

__device__ __forceinline__ float elu1f(float v) { return v > 0.f ? v : expm1f(v); }
__device__ __forceinline__ float lrelu(float v) { return v > 0.f ? v : 0.2f * v; }

__device__ __forceinline__ void load_edge(const int* __restrict__ ei, int e,
                                          int& src, int& dst) {
    if (e >= EE) { src = e - EE; dst = src; return; }
    src = ei[e]; dst = ei[EE + e];
}

// ---------------- CSR build ---------------------------------------------------
__global__ __launch_bounds__(256) void k_degzero() {
    int i = blockIdx.x * 256 + threadIdx.x;
    if (i < NN) g_degi[i] = 0;
}

__global__ __launch_bounds__(256) void k_deg(const int* __restrict__ ei) {
    int e = blockIdx.x * 256 + threadIdx.x;
    if (e >= EE) return;
    atomicAdd(&g_degi[ei[EE + e]], 1);
}

__global__ __launch_bounds__(256) void k_scan1() {
    int t = threadIdx.x, b = blockIdx.x;
    int idx = b * 256 + t;
    int val = (idx < NN) ? (g_degi[idx] + 1) : 0;
    __shared__ int s[256];
    s[t] = val;
    __syncthreads();
    for (int off = 1; off < 256; off <<= 1) {
        int v = (t >= off) ? s[t - off] : 0;
        __syncthreads();
        s[t] += v;
        __syncthreads();
    }
    if (idx < NN) g_rowptr[idx] = s[t] - val;
    if (t == 255) g_bsum[b] = s[255];
}

__global__ void k_scan2() {
    int t = threadIdx.x;   // 512
    __shared__ int s[512];
    int v = (t < NBLK) ? g_bsum[t] : 0;
    s[t] = v;
    __syncthreads();
    for (int off = 1; off < 512; off <<= 1) {
        int u = (t >= off) ? s[t - off] : 0;
        __syncthreads();
        s[t] += u;
        __syncthreads();
    }
    if (t < NBLK) g_bsum[t] = s[t] - v;
}

__global__ __launch_bounds__(256) void k_scan3() {
    int idx = blockIdx.x * 256 + threadIdx.x;
    if (idx < NN) {
        int r = g_rowptr[idx] + g_bsum[blockIdx.x];
        g_rowptr[idx] = r;
        g_cursor[idx] = r;
    }
    if (idx == 0) g_rowptr[NN] = EP;
}

__global__ __launch_bounds__(256) void k_fill(const int* __restrict__ ei) {
    int e = blockIdx.x * 256 + threadIdx.x;
    if (e >= EP) return;
    int src, dst;
    load_edge(ei, e, src, dst);
    int pos = atomicAdd(&g_cursor[dst], 1);
    g_cpack[pos] = make_int2(src, e);
}

// ---------------- precompute --------------------------------------------------
__global__ void k_ve(const float* __restrict__ W1e, const float* __restrict__ a1e,
                     const float* __restrict__ W2e, const float* __restrict__ a2e) {
    int t = threadIdx.x;
    if (t < EDD * HH) {
        int k = t / HH, h = t % HH;
        float s = 0.f;
        for (int c = 0; c < CC; c++) s += W1e[k * HC + h * CC + c] * a1e[h * CC + c];
        g_ve1[k * HH + h] = s;
    } else if (t < EDD * HH + EDD) {
        int k = t - EDD * HH;
        float s = 0.f;
        for (int c = 0; c < CC; c++) s += W2e[k * CC + c] * a2e[c];
        g_ve2[k] = s;
    }
}

__global__ __launch_bounds__(256) void k_edot(const float* __restrict__ eattr) {
    int e = blockIdx.x * 256 + threadIdx.x;
    if (e >= EE) return;
    const float4* ap = (const float4*)(eattr + (size_t)e * EDD);
    float a[EDD];
    #pragma unroll
    for (int q = 0; q < 4; q++) {
        float4 v = ap[q];
        a[q * 4 + 0] = v.x; a[q * 4 + 1] = v.y; a[q * 4 + 2] = v.z; a[q * 4 + 3] = v.w;
    }
    float4 d1 = make_float4(0.f, 0.f, 0.f, 0.f);
    float d2 = 0.f;
    #pragma unroll
    for (int k = 0; k < EDD; k++) {
        d1.x += a[k] * g_ve1[k * HH + 0];
        d1.y += a[k] * g_ve1[k * HH + 1];
        d1.z += a[k] * g_ve1[k * HH + 2];
        d1.w += a[k] * g_ve1[k * HH + 3];
        d2   += a[k] * g_ve2[k];
    }
    *(float4*)(g_edot1 + (size_t)e * HH) = d1;
    g_edot2[e] = d2;
}

// self-loop dots = segment mean (dot linear in attr)
__global__ __launch_bounds__(256) void k_sdot() {
    int w = (blockIdx.x * 256 + threadIdx.x) >> 5;
    if (w >= NN) return;
    int lane = threadIdx.x & 31;
    if (lane >= 5) return;
    int beg = g_rowptr[w], end = g_rowptr[w + 1];
    float inv = 1.f / fmaxf((float)(end - beg - 1), 1.f);
    float s = 0.f;
    for (int i = beg; i < end; i++) {
        int e = g_cpack[i].y;
        if (e < EE)
            s += (lane < 4) ? g_edot1[(size_t)e * HH + lane] : g_edot2[e];
    }
    if (lane < 4) g_sdot1[(size_t)w * HH + lane] = s * inv;
    else          g_sdot2[w] = s * inv;
}

// ---------------- tiled SGEMM (K = 128 fixed, N = BN) -------------------------
template <int BM, int BN, int BK, int TM, int TN>
__global__ __launch_bounds__((BM / TM) * (BN / TN)) void k_gemm_t(
    const float* __restrict__ A, const float* __restrict__ W,
    float* __restrict__ O, int M) {
    constexpr int THREADS = (BM / TM) * (BN / TN);
    constexpr int K = 128;
    __shared__ float As[BK][BM];
    __shared__ float Ws[BK][BN];
    int tid = threadIdx.x;
    int tcol = tid % (BN / TN);
    int trow = tid / (BN / TN);
    int m0 = blockIdx.x * BM;
    float acc[TM][TN] = {};
    for (int k0 = 0; k0 < K; k0 += BK) {
        #pragma unroll
        for (int q = 0; q < BM * BK / 4 / THREADS; q++) {
            int lin = (tid + q * THREADS) * 4;
            int r = lin / BK, c = lin % BK;
            float4 v = make_float4(0.f, 0.f, 0.f, 0.f);
            if (m0 + r < M) v = *(const float4*)(A + (size_t)(m0 + r) * K + k0 + c);
            As[c + 0][r] = v.x; As[c + 1][r] = v.y;
            As[c + 2][r] = v.z; As[c + 3][r] = v.w;
        }
        #pragma unroll
        for (int q = 0; q < BK * BN / 4 / THREADS; q++) {
            int lin = (tid + q * THREADS) * 4;
            int r = lin / BN, c = lin % BN;
            *(float4*)(&Ws[r][c]) = *(const float4*)(W + (size_t)(k0 + r) * BN + c);
        }
        __syncthreads();
        #pragma unroll
        for (int k = 0; k < BK; k++) {
            float a[TM], w[TN];
            #pragma unroll
            for (int i = 0; i < TM; i++) a[i] = As[k][trow * TM + i];
            #pragma unroll
            for (int j = 0; j < TN; j++) w[j] = Ws[k][tcol * TN + j];
            #pragma unroll
            for (int i = 0; i < TM; i++)
                #pragma unroll
                for (int j = 0; j < TN; j++)
                    acc[i][j] += a[i] * w[j];
        }
        __syncthreads();
    }
    #pragma unroll
    for (int i = 0; i < TM; i++) {
        int m = m0 + trow * TM + i;
        if (m < M) {
            #pragma unroll
            for (int j = 0; j < TN; j++)
                O[(size_t)m * BN + tcol * TN + j] = acc[i][j];
        }
    }
}

// ---------------- attention dot epilogues -------------------------------------
__global__ __launch_bounds__(256) void k_alsd1(const float* __restrict__ a1s,
                                               const float* __restrict__ a1d) {
    int w = (blockIdx.x * 256 + threadIdx.x) >> 5;
    if (w >= NN) return;
    int lane = threadIdx.x & 31;
    float4 f = *(const float4*)(g_feat1 + (size_t)w * HC + lane * 4);
    float4 s = *(const float4*)(a1s + lane * 4);
    float4 d = *(const float4*)(a1d + lane * 4);
    float ps = f.x * s.x + f.y * s.y + f.z * s.z + f.w * s.w;
    float pd = f.x * d.x + f.y * d.y + f.z * d.z + f.w * d.w;
    for (int off = 4; off; off >>= 1) {
        ps += __shfl_down_sync(0xffffffffu, ps, off, 8);
        pd += __shfl_down_sync(0xffffffffu, pd, off, 8);
    }
    if ((lane & 7) == 0) {
        int h = lane >> 3;
        g_als1[(size_t)w * HH + h] = ps;
        g_ald1[(size_t)w * HH + h] = pd;
    }
}

__global__ __launch_bounds__(256) void k_alsd2(const float* __restrict__ a2s,
                                               const float* __restrict__ a2d) {
    int w = (blockIdx.x * 256 + threadIdx.x) >> 5;
    if (w >= NN) return;
    int lane = threadIdx.x & 31;
    float f = g_feat2[(size_t)w * CC + lane];
    float ps = f * a2s[lane], pd = f * a2d[lane];
    for (int off = 16; off; off >>= 1) {
        ps += __shfl_down_sync(0xffffffffu, ps, off);
        pd += __shfl_down_sync(0xffffffffu, pd, off);
    }
    if (lane == 0) { g_als2[w] = ps; g_ald2[w] = pd; }
}

// ---------------- node gathers with fused logits ------------------------------
// warp per node: inline p = exp(lrelu(als1[src]+ald1[w]+edot1[e])) per subwarp
__global__ __launch_bounds__(256) void k_node1(const float* __restrict__ b1) {
    int w = (blockIdx.x * 256 + threadIdx.x) >> 5;
    if (w >= NN) return;
    int lane = threadIdx.x & 31, head = lane >> 3;
    float ald = g_ald1[(size_t)w * HH + head];
    int beg = g_rowptr[w], end = g_rowptr[w + 1];
    float z = 0.f;
    float4 acc = make_float4(0.f, 0.f, 0.f, 0.f);
    for (int i = beg; i < end; i++) {
        int2 pk = g_cpack[i];
        float ed = (pk.y < EE) ? g_edot1[(size_t)pk.y * HH + head]
                               : g_sdot1[(size_t)(pk.y - EE) * HH + head];
        float as = g_als1[(size_t)pk.x * HH + head];
        float p = __expf(lrelu(as + ald + ed));
        float4 v = *(const float4*)(g_feat1 + (size_t)pk.x * HC + lane * 4);
        z += p;
        acc.x += p * v.x; acc.y += p * v.y;
        acc.z += p * v.z; acc.w += p * v.w;
    }
    float inv = 1.f / fmaxf(z, 1e-30f);
    float4 bb = *(const float4*)(b1 + lane * 4);
    acc.x = elu1f(acc.x * inv + bb.x);
    acc.y = elu1f(acc.y * inv + bb.y);
    acc.z = elu1f(acc.z * inv + bb.z);
    acc.w = elu1f(acc.w * inv + bb.w);
    *(float4*)(g_h1 + (size_t)w * HC + lane * 4) = acc;
}

// warp per node (lane = feature): inline p; lane0 scatters p to g_eb2[eid]
__global__ __launch_bounds__(256) void k_node2(const float* __restrict__ b2,
                                               float* __restrict__ h2out) {
    int w = (blockIdx.x * 256 + threadIdx.x) >> 5;
    if (w >= NN) return;
    int lane = threadIdx.x & 31;
    float ald = g_ald2[w];
    int beg = g_rowptr[w], end = g_rowptr[w + 1];
    float z = 0.f, acc = 0.f;
    for (int i = beg; i < end; i++) {
        int2 pk = g_cpack[i];
        float ed = (pk.y < EE) ? g_edot2[pk.y] : g_sdot2[pk.y - EE];
        float p = __expf(lrelu(g_als2[pk.x] + ald + ed));
        z += p;
        acc += p * g_feat2[(size_t)pk.x * CC + lane];
        if (lane == 0) g_eb2[pk.y] = p;
    }
    z = fmaxf(z, 1e-30f);
    h2out[(size_t)w * CC + lane] = elu1f(acc / z + b2[lane]);
    if (lane == 0) g_z2[w] = z;
}

// ---------------- merged auxiliary outputs ------------------------------------
__global__ __launch_bounds__(256) void k_aux(const int* __restrict__ ei,
                                             float* __restrict__ alpha_out,
                                             float* __restrict__ ei_out) {
    int e = blockIdx.x * 256 + threadIdx.x;
    if (e >= EP) return;
    int src, dst;
    load_edge(ei, e, src, dst);
    alpha_out[e] = g_eb2[e] / g_z2[dst];
    if (ei_out != nullptr) {
        ei_out[e] = (float)src;
        ei_out[(size_t)EP + e] = (float)dst;
    }
}

// ---------------- launch -------------------------------------------------------
extern "C" void kernel_launch(void* const* d_in, const int* in_sizes, int n_in,
                              void* d_out, int out_size) {
    const float* x = nullptr; const int* ei = nullptr; const float* eatt = nullptr;
    const float* W1 = nullptr; const float* W1e = nullptr;
    const float* W2 = nullptr; const float* W2e = nullptr;
    const float* v128[4] = {}; int n128 = 0;
    const float* v32[4]  = {}; int n32 = 0;
    for (int i = 0; i < n_in; i++) {
        int s = in_sizes[i];
        const void* p = d_in[i];
        switch (s) {
            case NN * 128:  x    = (const float*)p; break;
            case 2 * EE:    ei   = (const int*)p;   break;
            case EE * EDD:  eatt = (const float*)p; break;
            case 128 * 128: W1   = (const float*)p; break;
            case EDD * 128: W1e  = (const float*)p; break;
            case 128 * 32:  W2   = (const float*)p; break;
            case EDD * 32:  W2e  = (const float*)p; break;
            case 128:       if (n128 < 4) v128[n128++] = (const float*)p; break;
            case 32:        if (n32  < 4) v32 [n32++]  = (const float*)p; break;
            default: break;
        }
    }
    const float* a1s = v128[0]; const float* a1d = v128[1];
    const float* b1  = v128[3];
    const float* a2s = v32[0];  const float* a2d = v32[1];
    const float* b2  = v32[3];
    const float* a1e = v128[2]; const float* a2e = v32[2];
    float* out = (float*)d_out;

    const size_t S_H2 = (size_t)NN * CC;
    const size_t S_EI = (size_t)2 * EP;
    const size_t S_AL = (size_t)EP;
    size_t osz = (size_t)out_size;
    float* out_h2    = out;
    float* out_ei    = nullptr;
    float* out_alpha = nullptr;
    if (osz >= S_H2 + S_EI + S_AL)      { out_ei = out + S_H2; out_alpha = out + S_H2 + S_EI; }
    else if (osz >= S_H2 + S_EI)        { out_ei = out + S_H2; }
    else if (osz >= S_H2 + S_AL)        { out_alpha = out + S_H2; }
    float* alpha_sink = out_alpha;
    if (alpha_sink == nullptr) {
        void* p = nullptr;
        cudaGetSymbolAddress(&p, g_alpha_scratch);
        alpha_sink = (float*)p;
    }
    void *p_feat1 = nullptr, *p_h1 = nullptr, *p_feat2 = nullptr;
    cudaGetSymbolAddress(&p_feat1, g_feat1);
    cudaGetSymbolAddress(&p_h1,    g_h1);
    cudaGetSymbolAddress(&p_feat2, g_feat2);

    const int T = 256;
    // Launch order puts gemm1 at slot 4 (ncu -s 5 lands there).
    k_degzero<<<(NN + T - 1) / T, T>>>();
    k_deg<<<(EE + T - 1) / T, T>>>(ei);
    k_ve<<<1, 128>>>(W1e, a1e, W2e, a2e);
    k_gemm_t<128, 128, 16, 8, 8><<<(NN + 127) / 128, 256>>>(x, W1, (float*)p_feat1, NN);
    k_scan1<<<NBLK, T>>>();
    k_scan2<<<1, 512>>>();
    k_scan3<<<NBLK, T>>>();
    k_fill<<<(EP + T - 1) / T, T>>>(ei);
    k_edot<<<(EE + T - 1) / T, T>>>(eatt);
    k_sdot<<<(NN * 32 + T - 1) / T, T>>>();

    // layer 1
    k_alsd1<<<(NN * 32 + T - 1) / T, T>>>(a1s, a1d);
    k_node1<<<(NN * 32 + T - 1) / T, T>>>(b1);

    // layer 2
    k_gemm_t<128, 32, 32, 8, 2><<<(NN + 127) / 128, 256>>>((const float*)p_h1, W2, (float*)p_feat2, NN);
    k_alsd2<<<(NN * 32 + T - 1) / T, T>>>(a2s, a2d);
    k_node2<<<(NN * 32 + T - 1) / T, T>>>(b2, out_h2);

    // auxiliary outputs (merged)
    k_aux<<<(EP + T - 1) / T, T>>>(ei, alpha_sink, out_ei);
}

// round 17
// speedup vs baseline: 1.1298x; 1.1298x over previous
#include <cuda_runtime.h>
#include <cuda_fp16.h>
#include <cstdint>

#define NN   100000
#define EE   1600000
#define EP   1700000   // EE + NN self loops
#define HH   4
#define CC   32
#define HC   128
#define EDD  16
#define NBLK ((NN + 255) / 256)

// ---------------- scratch: device symbols -----------------------------------
static __device__ int   g_degi[NN];
static __device__ int   g_bsum[NBLK];
static __device__ int   g_rowptr[NN + 1];
static __device__ int   g_cursor[NN];
static __device__ __align__(8) int2 g_cpack[EP];                 // (src, eid)
static __device__ __align__(16) float g_edot1[(size_t)EE * HH];
static __device__ float g_edot2[EE];
static __device__ __align__(16) float g_sdot1[(size_t)NN * HH];
static __device__ float g_sdot2[NN];
static __device__ __align__(16) __half g_feat1h[(size_t)NN * HC];  // fp16 feat1
static __device__ __align__(16) float  g_h1[(size_t)NN * HC];
static __device__ __align__(16) __half g_feat2h[(size_t)NN * CC];  // fp16 feat2
static __device__ __align__(16) float g_als1[(size_t)NN * HH];
static __device__ __align__(16) float g_ald1[(size_t)NN * HH];
static __device__ float g_als2[NN];
static __device__ float g_ald2[NN];
static __device__ __align__(16) float g_eb1[(size_t)EP * HH];    // p1
static __device__ float g_eb2[EP];                                // p2
static __device__ float g_z2[NN];
static __device__ float g_ve1[EDD * HH];
static __device__ float g_ve2[EDD];
static __device__ float g_alpha_scratch[EP];

__device__ __forceinline__ float elu1f(float v) { return v > 0.f ? v : expm1f(v); }
__device__ __forceinline__ float lrelu(float v) { return v > 0.f ? v : 0.2f * v; }

__device__ __forceinline__ void load_edge(const int* __restrict__ ei, int e,
                                          int& src, int& dst) {
    if (e >= EE) { src = e - EE; dst = src; return; }
    src = ei[e]; dst = ei[EE + e];
}

template <typename OT> __device__ __forceinline__ OT cvt_o(float v);
template <> __device__ __forceinline__ float  cvt_o<float>(float v)  { return v; }
template <> __device__ __forceinline__ __half cvt_o<__half>(float v) { return __float2half_rn(v); }

// ---------------- CSR build ---------------------------------------------------
__global__ __launch_bounds__(256) void k_degzero() {
    int i = blockIdx.x * 256 + threadIdx.x;
    if (i < NN) g_degi[i] = 0;
}

__global__ __launch_bounds__(256) void k_deg(const int* __restrict__ ei) {
    int e = blockIdx.x * 256 + threadIdx.x;
    if (e >= EE) return;
    atomicAdd(&g_degi[ei[EE + e]], 1);
}

__global__ __launch_bounds__(256) void k_scan1() {
    int t = threadIdx.x, b = blockIdx.x;
    int idx = b * 256 + t;
    int val = (idx < NN) ? (g_degi[idx] + 1) : 0;
    __shared__ int s[256];
    s[t] = val;
    __syncthreads();
    for (int off = 1; off < 256; off <<= 1) {
        int v = (t >= off) ? s[t - off] : 0;
        __syncthreads();
        s[t] += v;
        __syncthreads();
    }
    if (idx < NN) g_rowptr[idx] = s[t] - val;
    if (t == 255) g_bsum[b] = s[255];
}

__global__ void k_scan2() {
    int t = threadIdx.x;   // 512
    __shared__ int s[512];
    int v = (t < NBLK) ? g_bsum[t] : 0;
    s[t] = v;
    __syncthreads();
    for (int off = 1; off < 512; off <<= 1) {
        int u = (t >= off) ? s[t - off] : 0;
        __syncthreads();
        s[t] += u;
        __syncthreads();
    }
    if (t < NBLK) g_bsum[t] = s[t] - v;
}

__global__ __launch_bounds__(256) void k_scan3() {
    int idx = blockIdx.x * 256 + threadIdx.x;
    if (idx < NN) {
        int r = g_rowptr[idx] + g_bsum[blockIdx.x];
        g_rowptr[idx] = r;
        g_cursor[idx] = r;
    }
    if (idx == 0) g_rowptr[NN] = EP;
}

__global__ __launch_bounds__(256) void k_fill(const int* __restrict__ ei) {
    int e = blockIdx.x * 256 + threadIdx.x;
    if (e >= EP) return;
    int src, dst;
    load_edge(ei, e, src, dst);
    int pos = atomicAdd(&g_cursor[dst], 1);
    g_cpack[pos] = make_int2(src, e);
}

// ---------------- precompute --------------------------------------------------
__global__ void k_ve(const float* __restrict__ W1e, const float* __restrict__ a1e,
                     const float* __restrict__ W2e, const float* __restrict__ a2e) {
    int t = threadIdx.x;
    if (t < EDD * HH) {
        int k = t / HH, h = t % HH;
        float s = 0.f;
        for (int c = 0; c < CC; c++) s += W1e[k * HC + h * CC + c] * a1e[h * CC + c];
        g_ve1[k * HH + h] = s;
    } else if (t < EDD * HH + EDD) {
        int k = t - EDD * HH;
        float s = 0.f;
        for (int c = 0; c < CC; c++) s += W2e[k * CC + c] * a2e[c];
        g_ve2[k] = s;
    }
}

__global__ __launch_bounds__(256) void k_edot(const float* __restrict__ eattr) {
    int e = blockIdx.x * 256 + threadIdx.x;
    if (e >= EE) return;
    const float4* ap = (const float4*)(eattr + (size_t)e * EDD);
    float a[EDD];
    #pragma unroll
    for (int q = 0; q < 4; q++) {
        float4 v = ap[q];
        a[q * 4 + 0] = v.x; a[q * 4 + 1] = v.y; a[q * 4 + 2] = v.z; a[q * 4 + 3] = v.w;
    }
    float4 d1 = make_float4(0.f, 0.f, 0.f, 0.f);
    float d2 = 0.f;
    #pragma unroll
    for (int k = 0; k < EDD; k++) {
        d1.x += a[k] * g_ve1[k * HH + 0];
        d1.y += a[k] * g_ve1[k * HH + 1];
        d1.z += a[k] * g_ve1[k * HH + 2];
        d1.w += a[k] * g_ve1[k * HH + 3];
        d2   += a[k] * g_ve2[k];
    }
    *(float4*)(g_edot1 + (size_t)e * HH) = d1;
    g_edot2[e] = d2;
}

// self-loop dots = segment mean (dot linear in attr)
__global__ __launch_bounds__(256) void k_sdot() {
    int w = (blockIdx.x * 256 + threadIdx.x) >> 5;
    if (w >= NN) return;
    int lane = threadIdx.x & 31;
    if (lane >= 5) return;
    int beg = g_rowptr[w], end = g_rowptr[w + 1];
    float inv = 1.f / fmaxf((float)(end - beg - 1), 1.f);
    float s = 0.f;
    for (int i = beg; i < end; i++) {
        int e = g_cpack[i].y;
        if (e < EE)
            s += (lane < 4) ? g_edot1[(size_t)e * HH + lane] : g_edot2[e];
    }
    if (lane < 4) g_sdot1[(size_t)w * HH + lane] = s * inv;
    else          g_sdot2[w] = s * inv;
}

// ---------------- tiled SGEMM (K = 128 fixed), fp32 compute, OT output --------
template <int BM, int BN, int BK, int TM, int TN, typename OT>
__global__ __launch_bounds__((BM / TM) * (BN / TN)) void k_gemm_t(
    const float* __restrict__ A, const float* __restrict__ W,
    OT* __restrict__ O, int M) {
    constexpr int THREADS = (BM / TM) * (BN / TN);
    constexpr int K = 128;
    __shared__ float As[BK][BM];
    __shared__ float Ws[BK][BN];
    int tid = threadIdx.x;
    int tcol = tid % (BN / TN);
    int trow = tid / (BN / TN);
    int m0 = blockIdx.x * BM;
    float acc[TM][TN] = {};
    for (int k0 = 0; k0 < K; k0 += BK) {
        #pragma unroll
        for (int q = 0; q < BM * BK / 4 / THREADS; q++) {
            int lin = (tid + q * THREADS) * 4;
            int r = lin / BK, c = lin % BK;
            float4 v = make_float4(0.f, 0.f, 0.f, 0.f);
            if (m0 + r < M) v = *(const float4*)(A + (size_t)(m0 + r) * K + k0 + c);
            As[c + 0][r] = v.x; As[c + 1][r] = v.y;
            As[c + 2][r] = v.z; As[c + 3][r] = v.w;
        }
        #pragma unroll
        for (int q = 0; q < BK * BN / 4 / THREADS; q++) {
            int lin = (tid + q * THREADS) * 4;
            int r = lin / BN, c = lin % BN;
            *(float4*)(&Ws[r][c]) = *(const float4*)(W + (size_t)(k0 + r) * BN + c);
        }
        __syncthreads();
        #pragma unroll
        for (int k = 0; k < BK; k++) {
            float a[TM], w[TN];
            #pragma unroll
            for (int i = 0; i < TM; i++) a[i] = As[k][trow * TM + i];
            #pragma unroll
            for (int j = 0; j < TN; j++) w[j] = Ws[k][tcol * TN + j];
            #pragma unroll
            for (int i = 0; i < TM; i++)
                #pragma unroll
                for (int j = 0; j < TN; j++)
                    acc[i][j] += a[i] * w[j];
        }
        __syncthreads();
    }
    #pragma unroll
    for (int i = 0; i < TM; i++) {
        int m = m0 + trow * TM + i;
        if (m < M) {
            #pragma unroll
            for (int j = 0; j < TN; j++)
                O[(size_t)m * BN + tcol * TN + j] = cvt_o<OT>(acc[i][j]);
        }
    }
}

// ---------------- attention dot epilogues (fp16 feature reads) ----------------
__global__ __launch_bounds__(256) void k_alsd1(const float* __restrict__ a1s,
                                               const float* __restrict__ a1d) {
    int w = (blockIdx.x * 256 + threadIdx.x) >> 5;
    if (w >= NN) return;
    int lane = threadIdx.x & 31;
    uint2 u = *(const uint2*)(g_feat1h + (size_t)w * HC + lane * 4);
    float2 f01 = __half22float2(*reinterpret_cast<const __half2*>(&u.x));
    float2 f23 = __half22float2(*reinterpret_cast<const __half2*>(&u.y));
    float4 s = *(const float4*)(a1s + lane * 4);
    float4 d = *(const float4*)(a1d + lane * 4);
    float ps = f01.x * s.x + f01.y * s.y + f23.x * s.z + f23.y * s.w;
    float pd = f01.x * d.x + f01.y * d.y + f23.x * d.z + f23.y * d.w;
    for (int off = 4; off; off >>= 1) {
        ps += __shfl_down_sync(0xffffffffu, ps, off, 8);
        pd += __shfl_down_sync(0xffffffffu, pd, off, 8);
    }
    if ((lane & 7) == 0) {
        int h = lane >> 3;
        g_als1[(size_t)w * HH + h] = ps;
        g_ald1[(size_t)w * HH + h] = pd;
    }
}

__global__ __launch_bounds__(256) void k_alsd2(const float* __restrict__ a2s,
                                               const float* __restrict__ a2d) {
    int w = (blockIdx.x * 256 + threadIdx.x) >> 5;
    if (w >= NN) return;
    int lane = threadIdx.x & 31;
    float f = __half2float(g_feat2h[(size_t)w * CC + lane]);
    float ps = f * a2s[lane], pd = f * a2d[lane];
    for (int off = 16; off; off >>= 1) {
        ps += __shfl_down_sync(0xffffffffu, ps, off);
        pd += __shfl_down_sync(0xffffffffu, pd, off);
    }
    if (lane == 0) { g_als2[w] = ps; g_ald2[w] = pd; }
}

// ---------------- logits (shift-free p) ---------------------------------------
__global__ __launch_bounds__(256) void k_logits1(const int* __restrict__ ei) {
    int e = blockIdx.x * 256 + threadIdx.x;
    if (e >= EP) return;
    int src, dst;
    load_edge(ei, e, src, dst);
    float4 ed = (e < EE) ? *(const float4*)(g_edot1 + (size_t)e * HH)
                         : *(const float4*)(g_sdot1 + (size_t)(e - EE) * HH);
    float4 as = *(const float4*)(g_als1 + (size_t)src * HH);
    float4 ad = *(const float4*)(g_ald1 + (size_t)dst * HH);
    float4 p;
    p.x = __expf(lrelu(as.x + ad.x + ed.x));
    p.y = __expf(lrelu(as.y + ad.y + ed.y));
    p.z = __expf(lrelu(as.z + ad.z + ed.z));
    p.w = __expf(lrelu(as.w + ad.w + ed.w));
    *(float4*)(g_eb1 + (size_t)e * HH) = p;
}

__global__ __launch_bounds__(256) void k_logits2(const int* __restrict__ ei) {
    int e = blockIdx.x * 256 + threadIdx.x;
    if (e >= EP) return;
    int src, dst;
    load_edge(ei, e, src, dst);
    float ed = (e < EE) ? g_edot2[e] : g_sdot2[e - EE];
    g_eb2[e] = __expf(lrelu(g_als2[src] + g_ald2[dst] + ed));
}

// ---------------- node gathers (fp16 feature reads) ---------------------------
__global__ __launch_bounds__(256) void k_node1(const float* __restrict__ b1) {
    int w = (blockIdx.x * 256 + threadIdx.x) >> 5;
    if (w >= NN) return;
    int lane = threadIdx.x & 31, head = lane >> 3;
    int beg = g_rowptr[w], end = g_rowptr[w + 1];
    float z = 0.f;
    float4 acc = make_float4(0.f, 0.f, 0.f, 0.f);
    for (int i = beg; i < end; i++) {
        int2 pk = g_cpack[i];
        float p = g_eb1[(size_t)pk.y * HH + head];
        uint2 u = *(const uint2*)(g_feat1h + (size_t)pk.x * HC + lane * 4);
        float2 f01 = __half22float2(*reinterpret_cast<const __half2*>(&u.x));
        float2 f23 = __half22float2(*reinterpret_cast<const __half2*>(&u.y));
        z += p;
        acc.x += p * f01.x; acc.y += p * f01.y;
        acc.z += p * f23.x; acc.w += p * f23.y;
    }
    float inv = 1.f / fmaxf(z, 1e-30f);
    float4 bb = *(const float4*)(b1 + lane * 4);
    acc.x = elu1f(acc.x * inv + bb.x);
    acc.y = elu1f(acc.y * inv + bb.y);
    acc.z = elu1f(acc.z * inv + bb.z);
    acc.w = elu1f(acc.w * inv + bb.w);
    *(float4*)(g_h1 + (size_t)w * HC + lane * 4) = acc;
}

__global__ __launch_bounds__(256) void k_node2(const float* __restrict__ b2,
                                               float* __restrict__ h2out) {
    int w = (blockIdx.x * 256 + threadIdx.x) >> 5;
    if (w >= NN) return;
    int lane = threadIdx.x & 31;
    int beg = g_rowptr[w], end = g_rowptr[w + 1];
    float z = 0.f, acc = 0.f;
    for (int i = beg; i < end; i++) {
        int2 pk = g_cpack[i];
        float p = g_eb2[pk.y];
        z += p;
        acc += p * __half2float(g_feat2h[(size_t)pk.x * CC + lane]);
    }
    z = fmaxf(z, 1e-30f);
    h2out[(size_t)w * CC + lane] = elu1f(acc / z + b2[lane]);
    if (lane == 0) g_z2[w] = z;
}

// ---------------- merged auxiliary outputs ------------------------------------
__global__ __launch_bounds__(256) void k_aux(const int* __restrict__ ei,
                                             float* __restrict__ alpha_out,
                                             float* __restrict__ ei_out) {
    int e = blockIdx.x * 256 + threadIdx.x;
    if (e >= EP) return;
    int src, dst;
    load_edge(ei, e, src, dst);
    alpha_out[e] = g_eb2[e] / g_z2[dst];
    if (ei_out != nullptr) {
        ei_out[e] = (float)src;
        ei_out[(size_t)EP + e] = (float)dst;
    }
}

// ---------------- launch -------------------------------------------------------
extern "C" void kernel_launch(void* const* d_in, const int* in_sizes, int n_in,
                              void* d_out, int out_size) {
    const float* x = nullptr; const int* ei = nullptr; const float* eatt = nullptr;
    const float* W1 = nullptr; const float* W1e = nullptr;
    const float* W2 = nullptr; const float* W2e = nullptr;
    const float* v128[4] = {}; int n128 = 0;
    const float* v32[4]  = {}; int n32 = 0;
    for (int i = 0; i < n_in; i++) {
        int s = in_sizes[i];
        const void* p = d_in[i];
        switch (s) {
            case NN * 128:  x    = (const float*)p; break;
            case 2 * EE:    ei   = (const int*)p;   break;
            case EE * EDD:  eatt = (const float*)p; break;
            case 128 * 128: W1   = (const float*)p; break;
            case EDD * 128: W1e  = (const float*)p; break;
            case 128 * 32:  W2   = (const float*)p; break;
            case EDD * 32:  W2e  = (const float*)p; break;
            case 128:       if (n128 < 4) v128[n128++] = (const float*)p; break;
            case 32:        if (n32  < 4) v32 [n32++]  = (const float*)p; break;
            default: break;
        }
    }
    const float* a1s = v128[0]; const float* a1d = v128[1];
    const float* b1  = v128[3];
    const float* a2s = v32[0];  const float* a2d = v32[1];
    const float* b2  = v32[3];
    const float* a1e = v128[2]; const float* a2e = v32[2];
    float* out = (float*)d_out;

    const size_t S_H2 = (size_t)NN * CC;
    const size_t S_EI = (size_t)2 * EP;
    const size_t S_AL = (size_t)EP;
    size_t osz = (size_t)out_size;
    float* out_h2    = out;
    float* out_ei    = nullptr;
    float* out_alpha = nullptr;
    if (osz >= S_H2 + S_EI + S_AL)      { out_ei = out + S_H2; out_alpha = out + S_H2 + S_EI; }
    else if (osz >= S_H2 + S_EI)        { out_ei = out + S_H2; }
    else if (osz >= S_H2 + S_AL)        { out_alpha = out + S_H2; }
    float* alpha_sink = out_alpha;
    if (alpha_sink == nullptr) {
        void* p = nullptr;
        cudaGetSymbolAddress(&p, g_alpha_scratch);
        alpha_sink = (float*)p;
    }
    void *p_feat1h = nullptr, *p_h1 = nullptr, *p_feat2h = nullptr;
    cudaGetSymbolAddress(&p_feat1h, g_feat1h);
    cudaGetSymbolAddress(&p_h1,     g_h1);
    cudaGetSymbolAddress(&p_feat2h, g_feat2h);

    const int T = 256;
    // gemm1 stays in the ncu-profiled slot
    k_degzero<<<(NN + T - 1) / T, T>>>();
    k_deg<<<(EE + T - 1) / T, T>>>(ei);
    k_ve<<<1, 128>>>(W1e, a1e, W2e, a2e);
    k_gemm_t<128, 128, 32, 8, 8, __half><<<(NN + 127) / 128, 256>>>(x, W1, (__half*)p_feat1h, NN);
    k_scan1<<<NBLK, T>>>();
    k_scan2<<<1, 512>>>();
    k_scan3<<<NBLK, T>>>();
    k_fill<<<(EP + T - 1) / T, T>>>(ei);
    k_edot<<<(EE + T - 1) / T, T>>>(eatt);
    k_sdot<<<(NN * 32 + T - 1) / T, T>>>();

    // layer 1
    k_alsd1<<<(NN * 32 + T - 1) / T, T>>>(a1s, a1d);
    k_logits1<<<(EP + T - 1) / T, T>>>(ei);
    k_node1<<<(NN * 32 + T - 1) / T, T>>>(b1);

    // layer 2
    k_gemm_t<128, 32, 32, 8, 2, __half><<<(NN + 127) / 128, 256>>>((const float*)p_h1, W2, (__half*)p_feat2h, NN);
    k_alsd2<<<(NN * 32 + T - 1) / T, T>>>(a2s, a2d);
    k_logits2<<<(EP + T - 1) / T, T>>>(ei);
    k_node2<<<(NN * 32 + T - 1) / T, T>>>(b2, out_h2);

    // auxiliary outputs (merged)
    k_aux<<<(EP + T - 1) / T, T>>>(ei, alpha_sink, out_ei);
}